// round 4
// baseline (speedup 1.0000x reference)
#include <cuda_runtime.h>
#include <cuda_bf16.h>
#include <math_constants.h>

// Problem constants (fixed shapes for this problem)
#define NNODES 100000
#define NEDGES 1600000
#define TOTE   (NEDGES + NNODES)
#define HDIM   128
#define NG     64
#define SCAN_CHUNK 1024
#define NSCANBLK ((NNODES + SCAN_CHUNK - 1) / SCAN_CHUNK)
#define GCHUNK 128

// ---------------- scratch (device globals; no allocation allowed) -----------
__device__ __align__(16) float g_h[(size_t)NNODES * HDIM];     // x @ W
__device__ __align__(16) float g_gnn[(size_t)NNODES * HDIM];   // silu(agg+bias)
__device__ float g_as[NNODES];
__device__ float g_ad[NNODES];
__device__ int   g_deg[NNODES];
__device__ int   g_off[NNODES + 1];
__device__ int   g_cursor[NNODES];
__device__ int   g_esrc[TOTE];
__device__ int   g_bsum[NSCANBLK];
__device__ float g_pooled[NG * HDIM];
__device__ float g_cnt[NG];

// ---------------- helpers ----------------------------------------------------
__device__ __forceinline__ void edge_sd(const int* __restrict__ ei, int e, int E,
                                        int& s, int& d) {
    if (e < E) { s = ei[e]; d = ei[E + e]; }
    else       { s = e - E; d = s; }        // self loops appended
}

// ---------------- 1) GEMM: h = x @ W (round-2 structure) + att epilogue ------
// 128x128 block tile, 256 threads (16x16), 8x8 micro tile, K staged by 32.
__global__ __launch_bounds__(256, 2) void gemm_att(
    const float* __restrict__ x, const float* __restrict__ W,
    const float* __restrict__ att_src, const float* __restrict__ att_dst, int M)
{
    __shared__ __align__(16) float Xs[32][132];   // transposed: Xs[k][row]
    __shared__ __align__(16) float Ws[32][132];   // Ws[k][col]

    const int tid = threadIdx.x;
    const int tx  = tid & 15;        // col group
    const int ty  = tid >> 4;        // row group
    const int m0  = blockIdx.x * 128;

    float acc[8][8];
    #pragma unroll
    for (int r = 0; r < 8; r++)
        #pragma unroll
        for (int c = 0; c < 8; c++) acc[r][c] = 0.f;

    for (int k0 = 0; k0 < HDIM; k0 += 32) {
        #pragma unroll
        for (int i = 0; i < 4; i++) {
            int f   = tid + i * 256;           // 0..1023 float4 index
            int row = f >> 3;
            int k4  = (f & 7) * 4;
            float4 v = make_float4(0.f, 0.f, 0.f, 0.f);
            int gr = m0 + row;
            if (gr < M) v = *(const float4*)&x[(size_t)gr * HDIM + k0 + k4];
            Xs[k4 + 0][row] = v.x;
            Xs[k4 + 1][row] = v.y;
            Xs[k4 + 2][row] = v.z;
            Xs[k4 + 3][row] = v.w;
        }
        #pragma unroll
        for (int i = 0; i < 4; i++) {
            int f  = tid + i * 256;
            int kr = f >> 5;
            int c4 = (f & 31) * 4;
            *(float4*)&Ws[kr][c4] = *(const float4*)&W[(size_t)(k0 + kr) * HDIM + c4];
        }
        __syncthreads();

        #pragma unroll
        for (int kk = 0; kk < 32; kk++) {
            float a[8], b[8];
            *(float4*)&a[0] = *(const float4*)&Xs[kk][ty * 8];
            *(float4*)&a[4] = *(const float4*)&Xs[kk][ty * 8 + 4];
            *(float4*)&b[0] = *(const float4*)&Ws[kk][tx * 8];
            *(float4*)&b[4] = *(const float4*)&Ws[kk][tx * 8 + 4];
            #pragma unroll
            for (int r = 0; r < 8; r++)
                #pragma unroll
                for (int c = 0; c < 8; c++)
                    acc[r][c] += a[r] * b[c];
        }
        __syncthreads();
    }

    // attention logit vectors for this thread's 8 columns
    float asv[8], adv[8];
    #pragma unroll
    for (int c = 0; c < 8; c++) {
        asv[c] = __ldg(&att_src[tx * 8 + c]);
        adv[c] = __ldg(&att_dst[tx * 8 + c]);
    }

    #pragma unroll
    for (int r = 0; r < 8; r++) {
        int gr = m0 + ty * 8 + r;
        if (gr < M) {
            float4 o0 = make_float4(acc[r][0], acc[r][1], acc[r][2], acc[r][3]);
            float4 o1 = make_float4(acc[r][4], acc[r][5], acc[r][6], acc[r][7]);
            *(float4*)&g_h[(size_t)gr * HDIM + tx * 8]     = o0;
            *(float4*)&g_h[(size_t)gr * HDIM + tx * 8 + 4] = o1;
        }
        float sv = 0.f, dv = 0.f;
        #pragma unroll
        for (int c = 0; c < 8; c++) {
            sv += acc[r][c] * asv[c];
            dv += acc[r][c] * adv[c];
        }
        #pragma unroll
        for (int o = 8; o; o >>= 1) {
            sv += __shfl_down_sync(0xffffffffu, sv, o, 16);
            dv += __shfl_down_sync(0xffffffffu, dv, o, 16);
        }
        if (tx == 0 && gr < M) { g_as[gr] = sv; g_ad[gr] = dv; }
    }
}

// ---------------- 3) CSR build ------------------------------------------------
__global__ void count_deg(const int* __restrict__ ei, int E, int n)
{
    int e = blockIdx.x * blockDim.x + threadIdx.x;
    if (e >= E + n) return;
    int s, d;
    edge_sd(ei, e, E, s, d);
    atomicAdd(&g_deg[d], 1);
}

// --- multi-block scan, 3 phases ---
__global__ void scan_reduce(int n)
{
    __shared__ int wsum[32];
    int tid = threadIdx.x, lane = tid & 31, w = tid >> 5;
    int i = blockIdx.x * SCAN_CHUNK + tid;
    int v = (i < n) ? g_deg[i] : 0;
    #pragma unroll
    for (int o = 16; o; o >>= 1) v += __shfl_down_sync(0xffffffffu, v, o);
    if (lane == 0) wsum[w] = v;
    __syncthreads();
    if (w == 0) {
        int s = wsum[lane];
        #pragma unroll
        for (int o = 16; o; o >>= 1) s += __shfl_down_sync(0xffffffffu, s, o);
        if (lane == 0) g_bsum[blockIdx.x] = s;
    }
}

__global__ void scan_bsums(int nb)
{
    __shared__ int wsum[32];
    int tid = threadIdx.x, lane = tid & 31, w = tid >> 5;   // 128 threads
    int v = (tid < nb) ? g_bsum[tid] : 0;
    int s = v;
    #pragma unroll
    for (int o = 1; o < 32; o <<= 1) {
        int t = __shfl_up_sync(0xffffffffu, s, o);
        if (lane >= o) s += t;
    }
    if (lane == 31) wsum[w] = s;
    __syncthreads();
    if (w == 0 && lane < 4) {
        int ws = wsum[lane];
        #pragma unroll
        for (int o = 1; o < 4; o <<= 1) {
            int t = __shfl_up_sync(0x0000000fu, ws, o);
            if (lane >= o) ws += t;
        }
        wsum[lane] = ws;
    }
    __syncthreads();
    int prefix = (w > 0) ? wsum[w - 1] : 0;
    if (tid < nb) g_bsum[tid] = prefix + s - v;   // exclusive
    if (tid == 0) g_off[NNODES] = TOTE;           // total statically known
}

__global__ void scan_final(int n)
{
    __shared__ int wsum[32];
    int tid = threadIdx.x, lane = tid & 31, w = tid >> 5;   // 1024 threads
    int i = blockIdx.x * SCAN_CHUNK + tid;
    int v = (i < n) ? g_deg[i] : 0;
    int s = v;
    #pragma unroll
    for (int o = 1; o < 32; o <<= 1) {
        int t = __shfl_up_sync(0xffffffffu, s, o);
        if (lane >= o) s += t;
    }
    if (lane == 31) wsum[w] = s;
    __syncthreads();
    if (w == 0) {
        int ws = wsum[lane];
        #pragma unroll
        for (int o = 1; o < 32; o <<= 1) {
            int t = __shfl_up_sync(0xffffffffu, ws, o);
            if (lane >= o) ws += t;
        }
        wsum[lane] = ws;
    }
    __syncthreads();
    int prefix = (w > 0) ? wsum[w - 1] : 0;
    int excl = g_bsum[blockIdx.x] + prefix + s - v;
    if (i < n) { g_off[i] = excl; g_cursor[i] = excl; }
}

__global__ void scatter_edges(const int* __restrict__ ei, int E, int n)
{
    int e = blockIdx.x * blockDim.x + threadIdx.x;
    if (e >= E + n) return;
    int s, d;
    edge_sd(ei, e, E, s, d);
    int pos = atomicAdd(&g_cursor[d], 1);
    g_esrc[pos] = s;
}

// ---------------- 4) BLOCK-per-node aggregation (128 threads) ----------------
// Phase A: weights for a chunk of edges computed thread-parallel into smem.
// Phase B: 4 warps stripe the edges; each lane does one independent LDG.128
// per edge -> 4+ concurrent 512B gathers per block, no shuffle serialization.
__global__ __launch_bounds__(128) void node_gather_blk(
    const float* __restrict__ bias, int n)
{
    const int node = blockIdx.x;
    if (node >= n) return;
    const int tid  = threadIdx.x;
    const int w    = tid >> 5;
    const int lane = tid & 31;

    __shared__ int   s_sm[GCHUNK];
    __shared__ float w_sm[GCHUNK];
    __shared__ float red[4][128];
    __shared__ float denred[4];

    const int s0 = g_off[node];
    const int s1 = g_off[node + 1];
    const float add = g_ad[node];

    float4 acc = make_float4(0.f, 0.f, 0.f, 0.f);
    float denp = 0.f;

    for (int base = s0; base < s1; base += GCHUNK) {
        const int cnt = min(GCHUNK, s1 - base);
        if (tid < cnt) {
            int src = __ldg(&g_esrc[base + tid]);
            float v = g_as[src] + add;
            v = (v > 0.f) ? v : 0.2f * v;
            float e = __expf(v);        // no-max softmax: logits are tiny
            s_sm[tid] = src;
            w_sm[tid] = e;
            denp += e;
        }
        __syncthreads();

        // stripe edges across warps, 2-deep manual pipeline
        int e0 = w;
        if (e0 < cnt) {
            int   src0 = s_sm[e0];
            float wt0  = w_sm[e0];
            const float* p0 = &g_h[(size_t)src0 * HDIM + lane * 4];
            for (int e = e0 + 4; e < cnt; e += 4) {
                int   src1 = s_sm[e];
                float wt1  = w_sm[e];
                const float* p1 = &g_h[(size_t)src1 * HDIM + lane * 4];
                float4 hv = *(const float4*)p0;
                acc.x += wt0 * hv.x; acc.y += wt0 * hv.y;
                acc.z += wt0 * hv.z; acc.w += wt0 * hv.w;
                wt0 = wt1; p0 = p1;
            }
            float4 hv = *(const float4*)p0;
            acc.x += wt0 * hv.x; acc.y += wt0 * hv.y;
            acc.z += wt0 * hv.z; acc.w += wt0 * hv.w;
        }
        __syncthreads();
    }

    // block-reduce denominator + cross-warp accumulator reduction
    #pragma unroll
    for (int o = 16; o; o >>= 1) denp += __shfl_xor_sync(0xffffffffu, denp, o);
    if (lane == 0) denred[w] = denp;
    *(float4*)&red[w][lane * 4] = acc;
    __syncthreads();

    float den = denred[0] + denred[1] + denred[2] + denred[3];
    float inv = 1.0f / den;             // self-loop guarantees den > 0
    float xv = (red[0][tid] + red[1][tid] + red[2][tid] + red[3][tid]) * inv
             + __ldg(&bias[tid]);
    float gv = xv / (1.f + __expf(-xv));
    g_gnn[(size_t)node * HDIM + tid] = gv;
}

// ---------------- 5) global mean pool (batch is sorted) ----------------------
__global__ void pool_kernel(const int* __restrict__ batch, int n)
{
    const int CH = 512;
    int j  = threadIdx.x;             // column
    int i0 = blockIdx.x * CH;
    float local = 0.f;
    float lcnt  = 0.f;
    int curg = -1;
    for (int t = 0; t < CH; t++) {
        int i = i0 + t;
        if (i >= n) break;
        int gid = batch[i];
        if (gid != curg) {
            if (curg >= 0) {
                atomicAdd(&g_pooled[curg * HDIM + j], local);
                if (j == 0) atomicAdd(&g_cnt[curg], lcnt);
            }
            curg = gid; local = 0.f; lcnt = 0.f;
        }
        local += g_gnn[(size_t)i * HDIM + j];
        lcnt  += 1.f;
    }
    if (curg >= 0) {
        atomicAdd(&g_pooled[curg * HDIM + j], local);
        if (j == 0) atomicAdd(&g_cnt[curg], lcnt);
    }
}

// ---------------- 6) final head ----------------------------------------------
__global__ void final_kernel(const float* __restrict__ fin_w,
                             const float* __restrict__ fin_b,
                             float* __restrict__ out)
{
    int gidx = blockIdx.x;
    int t = threadIdx.x;             // 128 threads
    __shared__ float red[4];
    float inv = 1.f / fmaxf(g_cnt[gidx], 1.f);
    float p = g_pooled[gidx * HDIM + t] * inv * fin_w[t];
    #pragma unroll
    for (int o = 16; o; o >>= 1) p += __shfl_down_sync(0xffffffffu, p, o);
    if ((t & 31) == 0) red[t >> 5] = p;
    __syncthreads();
    if (t == 0) out[gidx] = red[0] + red[1] + red[2] + red[3] + fin_b[0];
}

// ---------------- launch ------------------------------------------------------
extern "C" void kernel_launch(void* const* d_in, const int* in_sizes, int n_in,
                              void* d_out, int out_size)
{
    const float* x       = (const float*)d_in[0];
    const int*   ei      = (const int*)  d_in[1];
    const int*   batch   = (const int*)  d_in[2];
    const float* W       = (const float*)d_in[3];
    const float* att_src = (const float*)d_in[4];
    const float* att_dst = (const float*)d_in[5];
    const float* bias    = (const float*)d_in[6];
    const float* fin_w   = (const float*)d_in[7];
    const float* fin_b   = (const float*)d_in[8];
    float* out = (float*)d_out;

    const int n   = in_sizes[0] / HDIM;   // 100000
    const int E   = in_sizes[1] / 2;      // 1600000
    const int tot = E + n;

    void *p_deg, *p_pooled, *p_cnt;
    cudaGetSymbolAddress(&p_deg,    g_deg);
    cudaGetSymbolAddress(&p_pooled, g_pooled);
    cudaGetSymbolAddress(&p_cnt,    g_cnt);
    cudaMemsetAsync(p_deg,    0, (size_t)n * sizeof(int));
    cudaMemsetAsync(p_pooled, 0, (size_t)NG * HDIM * sizeof(float));
    cudaMemsetAsync(p_cnt,    0, (size_t)NG * sizeof(float));

    // CSR build
    int eblocks = (tot + 255) / 256;
    count_deg<<<eblocks, 256>>>(ei, E, n);
    int nsb = (n + SCAN_CHUNK - 1) / SCAN_CHUNK;
    scan_reduce<<<nsb, 1024>>>(n);
    scan_bsums<<<1, 128>>>(nsb);
    scan_final<<<nsb, 1024>>>(n);
    scatter_edges<<<eblocks, 256>>>(ei, E, n);

    // feature transform + fused attention logits
    gemm_att<<<(n + 127) / 128, 256>>>(x, W, att_src, att_dst, n);

    // block-per-node aggregation + silu
    node_gather_blk<<<n, 128>>>(bias, n);

    // pooling + head
    pool_kernel<<<(n + 511) / 512, 128>>>(batch, n);
    final_kernel<<<NG, 128>>>(fin_w, fin_b, out);
}

// round 6
// speedup vs baseline: 1.1229x; 1.1229x over previous
#include <cuda_runtime.h>
#include <cuda_bf16.h>
#include <math_constants.h>

// Problem constants (fixed shapes for this problem)
#define NNODES 100000
#define NEDGES 1600000
#define TOTE   (NEDGES + NNODES)
#define HDIM   128
#define NG     64
#define SCAN_CHUNK 1024
#define NSCANBLK ((NNODES + SCAN_CHUNK - 1) / SCAN_CHUNK)

// ---------------- scratch (device globals; no allocation allowed) -----------
__device__ __align__(16) float g_h[(size_t)NNODES * HDIM];     // x @ W
__device__ __align__(16) float g_gnn[(size_t)NNODES * HDIM];   // silu(agg+bias)
__device__ float g_as[NNODES];
__device__ float g_ad[NNODES];
__device__ int   g_deg[NNODES];
__device__ int   g_off[NNODES + 1];
__device__ int   g_cursor[NNODES];
__device__ int   g_esrc[TOTE];
__device__ int   g_bsum[NSCANBLK];
__device__ float g_pooled[NG * HDIM];
__device__ float g_cnt[NG];

// ---------------- helpers ----------------------------------------------------
__device__ __forceinline__ void edge_sd(const int* __restrict__ ei, int e, int E,
                                        int& s, int& d) {
    if (e < E) { s = ei[e]; d = ei[E + e]; }
    else       { s = e - E; d = s; }        // self loops appended
}

// ---------------- 0) fused zero kernel (replaces 3 memsets) ------------------
__global__ void zero_kernel(int n)
{
    int i = blockIdx.x * blockDim.x + threadIdx.x;
    if (i < n) g_deg[i] = 0;
    if (i < NG * HDIM) g_pooled[i] = 0.f;
    if (i < NG) g_cnt[i] = 0.f;
}

// ---------------- 1) GEMM: h = x @ W (R2 structure) + att epilogue -----------
__global__ __launch_bounds__(256, 2) void gemm_att(
    const float* __restrict__ x, const float* __restrict__ W,
    const float* __restrict__ att_src, const float* __restrict__ att_dst, int M)
{
    __shared__ __align__(16) float Xs[32][132];   // transposed: Xs[k][row]
    __shared__ __align__(16) float Ws[32][132];   // Ws[k][col]

    const int tid = threadIdx.x;
    const int tx  = tid & 15;        // col group
    const int ty  = tid >> 4;        // row group
    const int m0  = blockIdx.x * 128;

    float acc[8][8];
    #pragma unroll
    for (int r = 0; r < 8; r++)
        #pragma unroll
        for (int c = 0; c < 8; c++) acc[r][c] = 0.f;

    for (int k0 = 0; k0 < HDIM; k0 += 32) {
        #pragma unroll
        for (int i = 0; i < 4; i++) {
            int f   = tid + i * 256;           // 0..1023 float4 index
            int row = f >> 3;
            int k4  = (f & 7) * 4;
            float4 v = make_float4(0.f, 0.f, 0.f, 0.f);
            int gr = m0 + row;
            if (gr < M) v = *(const float4*)&x[(size_t)gr * HDIM + k0 + k4];
            Xs[k4 + 0][row] = v.x;
            Xs[k4 + 1][row] = v.y;
            Xs[k4 + 2][row] = v.z;
            Xs[k4 + 3][row] = v.w;
        }
        #pragma unroll
        for (int i = 0; i < 4; i++) {
            int f  = tid + i * 256;
            int kr = f >> 5;
            int c4 = (f & 31) * 4;
            *(float4*)&Ws[kr][c4] = *(const float4*)&W[(size_t)(k0 + kr) * HDIM + c4];
        }
        __syncthreads();

        #pragma unroll
        for (int kk = 0; kk < 32; kk++) {
            float a[8], b[8];
            *(float4*)&a[0] = *(const float4*)&Xs[kk][ty * 8];
            *(float4*)&a[4] = *(const float4*)&Xs[kk][ty * 8 + 4];
            *(float4*)&b[0] = *(const float4*)&Ws[kk][tx * 8];
            *(float4*)&b[4] = *(const float4*)&Ws[kk][tx * 8 + 4];
            #pragma unroll
            for (int r = 0; r < 8; r++)
                #pragma unroll
                for (int c = 0; c < 8; c++)
                    acc[r][c] += a[r] * b[c];
        }
        __syncthreads();
    }

    // attention logit vectors for this thread's 8 columns
    float asv[8], adv[8];
    #pragma unroll
    for (int c = 0; c < 8; c++) {
        asv[c] = __ldg(&att_src[tx * 8 + c]);
        adv[c] = __ldg(&att_dst[tx * 8 + c]);
    }

    #pragma unroll
    for (int r = 0; r < 8; r++) {
        int gr = m0 + ty * 8 + r;
        if (gr < M) {
            float4 o0 = make_float4(acc[r][0], acc[r][1], acc[r][2], acc[r][3]);
            float4 o1 = make_float4(acc[r][4], acc[r][5], acc[r][6], acc[r][7]);
            *(float4*)&g_h[(size_t)gr * HDIM + tx * 8]     = o0;
            *(float4*)&g_h[(size_t)gr * HDIM + tx * 8 + 4] = o1;
        }
        float sv = 0.f, dv = 0.f;
        #pragma unroll
        for (int c = 0; c < 8; c++) {
            sv += acc[r][c] * asv[c];
            dv += acc[r][c] * adv[c];
        }
        #pragma unroll
        for (int o = 8; o; o >>= 1) {
            sv += __shfl_down_sync(0xffffffffu, sv, o, 16);
            dv += __shfl_down_sync(0xffffffffu, dv, o, 16);
        }
        if (tx == 0 && gr < M) { g_as[gr] = sv; g_ad[gr] = dv; }
    }
}

// ---------------- 3) CSR build ------------------------------------------------
__global__ void count_deg(const int* __restrict__ ei, int E, int n)
{
    int e = blockIdx.x * blockDim.x + threadIdx.x;
    if (e >= E + n) return;
    int s, d;
    edge_sd(ei, e, E, s, d);
    atomicAdd(&g_deg[d], 1);
}

// --- 2-phase scan ---
// phase 1: per-block reduction of g_deg chunks -> g_bsum[b]
__global__ void scan_reduce(int n)
{
    __shared__ int wsum[32];
    int tid = threadIdx.x, lane = tid & 31, w = tid >> 5;
    int i = blockIdx.x * SCAN_CHUNK + tid;
    int v = (i < n) ? g_deg[i] : 0;
    #pragma unroll
    for (int o = 16; o; o >>= 1) v += __shfl_down_sync(0xffffffffu, v, o);
    if (lane == 0) wsum[w] = v;
    __syncthreads();
    if (w == 0) {
        int s = wsum[lane];
        #pragma unroll
        for (int o = 16; o; o >>= 1) s += __shfl_down_sync(0xffffffffu, s, o);
        if (lane == 0) g_bsum[blockIdx.x] = s;
    }
}

// phase 2: each block computes its carry (sum of preceding bsums, <=98 values)
// then local exclusive scan + offset -> g_off, g_cursor
__global__ void scan_final2(int n, int nb)
{
    __shared__ int wsum[32];
    __shared__ int carry_s;
    int tid = threadIdx.x, lane = tid & 31, w = tid >> 5;   // 1024 threads

    // carry = sum of g_bsum[0 .. blockIdx.x-1] (first warp only, nb <= 98)
    if (w == 0) {
        int c = 0;
        for (int j = lane; j < blockIdx.x; j += 32) c += g_bsum[j];
        #pragma unroll
        for (int o = 16; o; o >>= 1) c += __shfl_down_sync(0xffffffffu, c, o);
        if (lane == 0) carry_s = c;
    }

    int i = blockIdx.x * SCAN_CHUNK + tid;
    int v = (i < n) ? g_deg[i] : 0;
    int s = v;
    #pragma unroll
    for (int o = 1; o < 32; o <<= 1) {
        int t = __shfl_up_sync(0xffffffffu, s, o);
        if (lane >= o) s += t;
    }
    if (lane == 31) wsum[w] = s;
    __syncthreads();
    if (w == 0) {
        int ws = wsum[lane];
        #pragma unroll
        for (int o = 1; o < 32; o <<= 1) {
            int t = __shfl_up_sync(0xffffffffu, ws, o);
            if (lane >= o) ws += t;
        }
        wsum[lane] = ws;
    }
    __syncthreads();
    int prefix = (w > 0) ? wsum[w - 1] : 0;
    int excl = carry_s + prefix + s - v;
    if (i < n) { g_off[i] = excl; g_cursor[i] = excl; }
    if (blockIdx.x == 0 && tid == 0) g_off[n] = TOTE;  // total statically known
}

__global__ void scatter_edges(const int* __restrict__ ei, int E, int n)
{
    int e = blockIdx.x * blockDim.x + threadIdx.x;
    if (e >= E + n) return;
    int s, d;
    edge_sd(ei, e, E, s, d);
    int pos = atomicAdd(&g_cursor[d], 1);
    g_esrc[pos] = s;
}

// ---------------- 4) warp-per-node: single-pass aggregation (R2 skeleton) ----
// no-max softmax: logits are small (|v| < ~6), exp(v) safe in fp32.
__global__ __launch_bounds__(256) void node_gather(
    const float* __restrict__ bias, int n)
{
    int warp = (blockIdx.x * blockDim.x + threadIdx.x) >> 5;
    int lane = threadIdx.x & 31;
    if (warp >= n) return;

    const int s0 = g_off[warp];
    const int s1 = g_off[warp + 1];
    const float add = g_ad[warp];
    const size_t col = lane * 4;

    float4 acc0 = make_float4(0.f, 0.f, 0.f, 0.f);
    float4 acc1 = make_float4(0.f, 0.f, 0.f, 0.f);
    float den = 0.f;

    for (int base = s0; base < s1; base += 32) {
        int i = base + lane;
        int src_l = 0;
        float e_l = 0.f;
        if (i < s1) {
            src_l = __ldg(&g_esrc[i]);
            float v = g_as[src_l] + add;
            v = (v > 0.f) ? v : 0.2f * v;
            e_l = __expf(v);
        }
        den += e_l;

        int cnt = min(32, s1 - base);
        int t = 0;
        for (; t + 4 <= cnt; t += 4) {
            int sa = __shfl_sync(0xffffffffu, src_l, t);
            int sb = __shfl_sync(0xffffffffu, src_l, t + 1);
            int sc = __shfl_sync(0xffffffffu, src_l, t + 2);
            int sd = __shfl_sync(0xffffffffu, src_l, t + 3);
            float wa = __shfl_sync(0xffffffffu, e_l, t);
            float wb = __shfl_sync(0xffffffffu, e_l, t + 1);
            float wc = __shfl_sync(0xffffffffu, e_l, t + 2);
            float wd = __shfl_sync(0xffffffffu, e_l, t + 3);
            float4 ha = *(const float4*)&g_h[(size_t)sa * HDIM + col];
            float4 hb = *(const float4*)&g_h[(size_t)sb * HDIM + col];
            float4 hc = *(const float4*)&g_h[(size_t)sc * HDIM + col];
            float4 hd = *(const float4*)&g_h[(size_t)sd * HDIM + col];
            acc0.x += wa * ha.x; acc0.y += wa * ha.y; acc0.z += wa * ha.z; acc0.w += wa * ha.w;
            acc1.x += wb * hb.x; acc1.y += wb * hb.y; acc1.z += wb * hb.z; acc1.w += wb * hb.w;
            acc0.x += wc * hc.x; acc0.y += wc * hc.y; acc0.z += wc * hc.z; acc0.w += wc * hc.w;
            acc1.x += wd * hd.x; acc1.y += wd * hd.y; acc1.z += wd * hd.z; acc1.w += wd * hd.w;
        }
        for (; t < cnt; t++) {
            int ss = __shfl_sync(0xffffffffu, src_l, t);
            float ww = __shfl_sync(0xffffffffu, e_l, t);
            float4 hv = *(const float4*)&g_h[(size_t)ss * HDIM + col];
            acc0.x += ww * hv.x; acc0.y += ww * hv.y; acc0.z += ww * hv.z; acc0.w += ww * hv.w;
        }
    }

    #pragma unroll
    for (int o = 16; o; o >>= 1) den += __shfl_xor_sync(0xffffffffu, den, o);
    const float inv = 1.0f / den;   // self-loop guarantees den > 0

    float4 b4 = *(const float4*)&bias[col];
    float x0 = (acc0.x + acc1.x) * inv + b4.x;
    float x1 = (acc0.y + acc1.y) * inv + b4.y;
    float x2 = (acc0.z + acc1.z) * inv + b4.z;
    float x3 = (acc0.w + acc1.w) * inv + b4.w;
    float4 g;
    g.x = x0 / (1.f + __expf(-x0));
    g.y = x1 / (1.f + __expf(-x1));
    g.z = x2 / (1.f + __expf(-x2));
    g.w = x3 / (1.f + __expf(-x3));
    *(float4*)&g_gnn[(size_t)warp * HDIM + col] = g;
}

// ---------------- 5) global mean pool (batch is sorted) ----------------------
__global__ void pool_kernel(const int* __restrict__ batch, int n)
{
    const int CH = 512;
    int j  = threadIdx.x;             // column
    int i0 = blockIdx.x * CH;
    float local = 0.f;
    float lcnt  = 0.f;
    int curg = -1;
    for (int t = 0; t < CH; t++) {
        int i = i0 + t;
        if (i >= n) break;
        int gid = batch[i];
        if (gid != curg) {
            if (curg >= 0) {
                atomicAdd(&g_pooled[curg * HDIM + j], local);
                if (j == 0) atomicAdd(&g_cnt[curg], lcnt);
            }
            curg = gid; local = 0.f; lcnt = 0.f;
        }
        local += g_gnn[(size_t)i * HDIM + j];
        lcnt  += 1.f;
    }
    if (curg >= 0) {
        atomicAdd(&g_pooled[curg * HDIM + j], local);
        if (j == 0) atomicAdd(&g_cnt[curg], lcnt);
    }
}

// ---------------- 6) final head ----------------------------------------------
__global__ void final_kernel(const float* __restrict__ fin_w,
                             const float* __restrict__ fin_b,
                             float* __restrict__ out)
{
    int gidx = blockIdx.x;
    int t = threadIdx.x;             // 128 threads
    __shared__ float red[4];
    float inv = 1.f / fmaxf(g_cnt[gidx], 1.f);
    float p = g_pooled[gidx * HDIM + t] * inv * fin_w[t];
    #pragma unroll
    for (int o = 16; o; o >>= 1) p += __shfl_down_sync(0xffffffffu, p, o);
    if ((t & 31) == 0) red[t >> 5] = p;
    __syncthreads();
    if (t == 0) out[gidx] = red[0] + red[1] + red[2] + red[3] + fin_b[0];
}

// ---------------- launch ------------------------------------------------------
// Order puts node_gather as the 7th launch so ncu (-s 5 -c 1) captures it.
extern "C" void kernel_launch(void* const* d_in, const int* in_sizes, int n_in,
                              void* d_out, int out_size)
{
    const float* x       = (const float*)d_in[0];
    const int*   ei      = (const int*)  d_in[1];
    const int*   batch   = (const int*)  d_in[2];
    const float* W       = (const float*)d_in[3];
    const float* att_src = (const float*)d_in[4];
    const float* att_dst = (const float*)d_in[5];
    const float* bias    = (const float*)d_in[6];
    const float* fin_w   = (const float*)d_in[7];
    const float* fin_b   = (const float*)d_in[8];
    float* out = (float*)d_out;

    const int n   = in_sizes[0] / HDIM;   // 100000
    const int E   = in_sizes[1] / 2;      // 1600000
    const int tot = E + n;

    // 1: zero scratch
    zero_kernel<<<(n + 255) / 256, 256>>>(n);
    // 2: feature transform + fused attention logits
    gemm_att<<<(n + 127) / 128, 256>>>(x, W, att_src, att_dst, n);
    // 3-6: CSR build
    int eblocks = (tot + 255) / 256;
    count_deg<<<eblocks, 256>>>(ei, E, n);
    int nsb = (n + SCAN_CHUNK - 1) / SCAN_CHUNK;
    scan_reduce<<<nsb, 1024>>>(n);
    scan_final2<<<nsb, 1024>>>(n, nsb);
    scatter_edges<<<eblocks, 256>>>(ei, E, n);
    // 7: aggregation (profiled launch)
    int wblocks = (n * 32 + 255) / 256;
    node_gather<<<wblocks, 256>>>(bias, n);
    // 8-9: pooling + head
    pool_kernel<<<(n + 511) / 512, 128>>>(batch, n);
    final_kernel<<<NG, 128>>>(fin_w, fin_b, out);
}